// round 7
// baseline (speedup 1.0000x reference)
#include <cuda_runtime.h>
#include <cstdint>

// ---------------------------------------------------------------------------
// Problem constants (B=2, C=192, H=W=256, WS=8, NH=6, hd=32, DF=768)
// ---------------------------------------------------------------------------
#define CH    192
#define NTOK  131072
#define DF    768
#define NWIN  2048
#define WN    64

// ---------------------------------------------------------------------------
// Scratch (static device allocations)
// ---------------------------------------------------------------------------
__device__ float d_perm [NTOK * CH];
__device__ float d_qkv  [NTOK * 3 * CH];
__device__ float d_obuf [NTOK * CH];
__device__ float d_ybuf [NTOK * CH];
__device__ float d_zt   [NTOK * CH];
__device__ float d_gbuf [NTOK * DF];
__device__ float d_qkvT [576 * 192];
__device__ float d_projT[192 * 192];
__device__ float d_wI   [1536 * 192];   // interleaved fc1/fc2

// ---------------------------------------------------------------------------
// mma.sync / cp.async helpers (portable PTX, no arch-a features)
// ---------------------------------------------------------------------------
__device__ __forceinline__ uint32_t cvt_tf32(float x) {
    uint32_t r;
    asm("cvt.rna.tf32.f32 %0, %1;" : "=r"(r) : "f"(x));
    return r;
}
__device__ __forceinline__ void mma_tf32(float* d, const uint32_t* a, const uint32_t* b) {
    asm volatile(
        "mma.sync.aligned.m16n8k8.row.col.f32.tf32.tf32.f32 "
        "{%0,%1,%2,%3},{%4,%5,%6,%7},{%8,%9},{%0,%1,%2,%3};"
        : "+f"(d[0]), "+f"(d[1]), "+f"(d[2]), "+f"(d[3])
        : "r"(a[0]), "r"(a[1]), "r"(a[2]), "r"(a[3]), "r"(b[0]), "r"(b[1]));
}
__device__ __forceinline__ void cp_async16(void* dst, const void* src) {
    uint32_t d = (uint32_t)__cvta_generic_to_shared(dst);
    asm volatile("cp.async.cg.shared.global [%0], [%1], 16;" :: "r"(d), "l"(src));
}
__device__ __forceinline__ void cp_commit() { asm volatile("cp.async.commit_group;"); }
template<int N>
__device__ __forceinline__ void cp_wait() { asm volatile("cp.async.wait_group %0;" :: "n"(N)); }

// ---------------------------------------------------------------------------
// Kernel 1: LN1 + channel-layout window partition. Block = one (b,h) row
// of 256 pixels; x row staged in smem so x is read from DRAM exactly once.
// ---------------------------------------------------------------------------
__global__ void ln1_kernel(const float* __restrict__ x,
                           const float* __restrict__ g,
                           const float* __restrict__ b,
                           float* __restrict__ perm)
{
    extern __shared__ float xs[];     // [192][256]
    const int tid = threadIdx.x;      // = w
    const int h  = blockIdx.x & 255;
    const int bb = blockIdx.x >> 8;
    const float* xp = x + (size_t)bb * CH * 65536 + h * 256 + tid;

    float sum = 0.f, sq = 0.f;
    #pragma unroll 4
    for (int c = 0; c < CH; c++) {
        float v = xp[(size_t)c * 65536];
        xs[c * 256 + tid] = v;
        sum += v; sq += v * v;
    }
    float mean = sum * (1.f / CH);
    float var  = sq * (1.f / CH) - mean * mean;
    float inv  = rsqrtf(fmaxf(var, 0.f) + 1e-5f);

    const int h1 = h >> 3, h2 = h & 7;
    #pragma unroll 4
    for (int c = 0; c < CH; c++) {
        float v = (xs[c * 256 + tid] - mean) * inv * g[c] + b[c];
        int c1 = c >> 3, c2 = c & 7;
        size_t P = (((((size_t)bb * 24 + c1) * 32 + h1) * 8 + c2) * 8 + h2) * 256 + tid;
        perm[P] = v;
    }
}

// ---------------------------------------------------------------------------
// Kernel 2: weight prep — transpose qkv_w/proj_w, interleave fc1/fc2 rows
// ---------------------------------------------------------------------------
__global__ void prep_w(const float* __restrict__ qw, const float* __restrict__ pw,
                       const float* __restrict__ f1, const float* __restrict__ f2,
                       float* __restrict__ qT, float* __restrict__ pT,
                       float* __restrict__ wI)
{
    int i = blockIdx.x * blockDim.x + threadIdx.x;
    if (i < 192 * 576) { int k = i / 576, n = i % 576; qT[n * 192 + k] = qw[i]; }
    if (i < 192 * 192) { int k = i / 192, n = i % 192; pT[n * 192 + k] = pw[i]; }
    if (i < 768 * 192) {
        int j = i / 192, k = i % 192;
        wI[(size_t)(2 * j)     * 192 + k] = f1[i];
        wI[(size_t)(2 * j + 1) * 192 + k] = f2[i];
    }
}

// ---------------------------------------------------------------------------
// K=192 GEMM with A resident in smem: C[M,N] = A[M,192] @ Bw[N,192]^T.
// Block: 128 threads, BM=128. Whole A tile (128x192, stride 196 = conflict-
// free) loaded once; loop over N in 64-col chunks with double-buffered B.
// A is read from DRAM exactly once regardless of N.
// EPI: 0 = +bias -> out[M,N]   (QKV)
//      1 = +bias + resid[m*N+n] -> out[M,N]   (proj + residual)
//      2 = gate pairs: sigmoid(c0+b1)*(c1+b2) -> out[M,768]  (gated FFN, wI)
// ---------------------------------------------------------------------------
#define AS_STRIDE 196
template<int EPI>
__global__ __launch_bounds__(128)
void gemm_k192(const float* __restrict__ A,  const float* __restrict__ Bw,
               const float* __restrict__ bias1, const float* __restrict__ bias2,
               const float* __restrict__ resid, float* __restrict__ out, int N)
{
    extern __shared__ float sm[];
    float* As = sm;                                   // [128][196]
    float* Bs = sm + 128 * AS_STRIDE;                 // [2][64][196]

    const int tid  = threadIdx.x;
    const int warp = tid >> 5, lane = tid & 31;
    const int g = lane >> 2, cq = lane & 3;
    const int wm = warp >> 1, wn = warp & 1;
    const int M0 = blockIdx.x * 128;
    const int K = 192;
    const int NCHUNK = N >> 6;

    // load A tile once: 128 rows x 48 float4
    #pragma unroll
    for (int it = 0; it < 48; it++) {
        int f = tid + it * 128;
        int row = f / 48, c4 = f % 48;
        cp_async16(&As[row * AS_STRIDE + c4 * 4], A + (size_t)(M0 + row) * K + c4 * 4);
    }
    cp_commit();
    // prefetch B chunk 0: 64 rows x 48 float4
    #pragma unroll
    for (int it = 0; it < 24; it++) {
        int f = tid + it * 128;
        int row = f / 48, c4 = f % 48;
        cp_async16(&Bs[row * AS_STRIDE + c4 * 4], Bw + (size_t)row * K + c4 * 4);
    }
    cp_commit();

    for (int n = 0; n < NCHUNK; n++) {
        if (n + 1 < NCHUNK) {
            const float* src = Bw + (size_t)(n + 1) * 64 * K;
            float* dst = Bs + ((n + 1) & 1) * 64 * AS_STRIDE;
            #pragma unroll
            for (int it = 0; it < 24; it++) {
                int f = tid + it * 128;
                int row = f / 48, c4 = f % 48;
                cp_async16(&dst[row * AS_STRIDE + c4 * 4], src + (size_t)row * K + c4 * 4);
            }
        }
        cp_commit();
        cp_wait<1>();          // chunk n (and A on first iter) complete
        __syncthreads();

        const float* Bc = Bs + (n & 1) * 64 * AS_STRIDE;
        float acc[4][4][4] = {};

        #pragma unroll 4
        for (int ks = 0; ks < 24; ks++) {
            uint32_t af[4][4], bf[4][2];
            #pragma unroll
            for (int mi = 0; mi < 4; mi++) {
                const float* ap = As + (wm * 64 + mi * 16 + g) * AS_STRIDE + ks * 8 + cq;
                af[mi][0] = cvt_tf32(ap[0]);
                af[mi][1] = cvt_tf32(ap[8 * AS_STRIDE]);
                af[mi][2] = cvt_tf32(ap[4]);
                af[mi][3] = cvt_tf32(ap[8 * AS_STRIDE + 4]);
            }
            #pragma unroll
            for (int ni = 0; ni < 4; ni++) {
                const float* bp = Bc + (wn * 32 + ni * 8 + g) * AS_STRIDE + ks * 8 + cq;
                bf[ni][0] = cvt_tf32(bp[0]);
                bf[ni][1] = cvt_tf32(bp[4]);
            }
            #pragma unroll
            for (int mi = 0; mi < 4; mi++)
                #pragma unroll
                for (int ni = 0; ni < 4; ni++)
                    mma_tf32(acc[mi][ni], af[mi], bf[ni]);
        }
        __syncthreads();       // compute done before next prefetch overwrites

        // ---- epilogue for this N-chunk ----
        const int N0 = n * 64;
        #pragma unroll
        for (int mi = 0; mi < 4; mi++) {
            #pragma unroll
            for (int ni = 0; ni < 4; ni++) {
                float* a4 = acc[mi][ni];
                const int m0 = M0 + wm * 64 + mi * 16 + g;
                const int m1 = m0 + 8;
                const int n0 = N0 + wn * 32 + ni * 8 + 2 * cq;

                if (EPI == 0) {
                    float b0 = bias1[n0], b1 = bias1[n0 + 1];
                    *(float2*)&out[(size_t)m0 * N + n0] = make_float2(a4[0] + b0, a4[1] + b1);
                    *(float2*)&out[(size_t)m1 * N + n0] = make_float2(a4[2] + b0, a4[3] + b1);
                } else if (EPI == 1) {
                    float b0 = bias1[n0], b1 = bias1[n0 + 1];
                    float2 r0 = *(const float2*)&resid[(size_t)m0 * N + n0];
                    float2 r1 = *(const float2*)&resid[(size_t)m1 * N + n0];
                    *(float2*)&out[(size_t)m0 * N + n0] =
                        make_float2(a4[0] + b0 + r0.x, a4[1] + b1 + r0.y);
                    *(float2*)&out[(size_t)m1 * N + n0] =
                        make_float2(a4[2] + b0 + r1.x, a4[3] + b1 + r1.y);
                } else { // EPI == 2: interleaved gate pair p at cols (2p, 2p+1)
                    int p = ((N0 + wn * 32 + ni * 8) >> 1) + cq;
                    float b1 = bias1[p], b2 = bias2[p];
                    float h1a = 1.f / (1.f + __expf(-(a4[0] + b1)));
                    float h1b = 1.f / (1.f + __expf(-(a4[2] + b1)));
                    out[(size_t)m0 * DF + p] = h1a * (a4[1] + b2);
                    out[(size_t)m1 * DF + p] = h1b * (a4[3] + b2);
                }
            }
        }
    }
}

// ---------------------------------------------------------------------------
// fc3 GEMM (K=768, N=192 in one block): out = gbuf @ fc3^T + bias + resid,
// scattered to (B,C,H,W). 256 threads, 8 warps (2x4), warp tile 64x48.
// gbuf is read from DRAM exactly once.
// ---------------------------------------------------------------------------
__global__ __launch_bounds__(256)
void gemm_out(const float* __restrict__ A, const float* __restrict__ Bw,
              const float* __restrict__ bias1, const float* __restrict__ resid,
              float* __restrict__ out)
{
    extern __shared__ float sm[];
    float* As = sm;                       // [2][128][20]
    float* Bs = sm + 2 * 128 * 20;        // [2][192][20]

    const int tid  = threadIdx.x;
    const int warp = tid >> 5, lane = tid & 31;
    const int g = lane >> 2, cq = lane & 3;
    const int wm = warp >> 2, wn = warp & 3;
    const int M0 = blockIdx.x * 128;
    const int K = 768, NC = 48;

    float acc[4][6][4] = {};

    // prefetch stage 0
    #pragma unroll
    for (int it = 0; it < 2; it++) {
        int f = tid + it * 256, row = f >> 2, vec = f & 3;
        cp_async16(&As[row * 20 + vec * 4], A + (size_t)(M0 + row) * K + vec * 4);
    }
    #pragma unroll
    for (int it = 0; it < 3; it++) {
        int f = tid + it * 256, row = f >> 2, vec = f & 3;
        cp_async16(&Bs[row * 20 + vec * 4], Bw + (size_t)row * K + vec * 4);
    }
    cp_commit();

    for (int c = 0; c < NC; c++) {
        if (c + 1 < NC) {
            const int s = (c + 1) & 1, k0 = (c + 1) << 4;
            #pragma unroll
            for (int it = 0; it < 2; it++) {
                int f = tid + it * 256, row = f >> 2, vec = f & 3;
                cp_async16(&As[s * 128 * 20 + row * 20 + vec * 4],
                           A + (size_t)(M0 + row) * K + k0 + vec * 4);
            }
            #pragma unroll
            for (int it = 0; it < 3; it++) {
                int f = tid + it * 256, row = f >> 2, vec = f & 3;
                cp_async16(&Bs[s * 192 * 20 + row * 20 + vec * 4],
                           Bw + (size_t)row * K + k0 + vec * 4);
            }
        }
        cp_commit();
        cp_wait<1>();
        __syncthreads();

        const float* Ac = As + (c & 1) * 128 * 20;
        const float* Bc = Bs + (c & 1) * 192 * 20;
        #pragma unroll
        for (int ks = 0; ks < 2; ks++) {
            uint32_t af[4][4], bf[6][2];
            #pragma unroll
            for (int mi = 0; mi < 4; mi++) {
                const float* ap = Ac + (wm * 64 + mi * 16 + g) * 20 + ks * 8 + cq;
                af[mi][0] = cvt_tf32(ap[0]);
                af[mi][1] = cvt_tf32(ap[8 * 20]);
                af[mi][2] = cvt_tf32(ap[4]);
                af[mi][3] = cvt_tf32(ap[8 * 20 + 4]);
            }
            #pragma unroll
            for (int ni = 0; ni < 6; ni++) {
                const float* bp = Bc + (wn * 48 + ni * 8 + g) * 20 + ks * 8 + cq;
                bf[ni][0] = cvt_tf32(bp[0]);
                bf[ni][1] = cvt_tf32(bp[4]);
            }
            #pragma unroll
            for (int mi = 0; mi < 4; mi++)
                #pragma unroll
                for (int ni = 0; ni < 6; ni++)
                    mma_tf32(acc[mi][ni], af[mi], bf[ni]);
        }
        __syncthreads();
    }

    // epilogue: +bias +resid, scatter to (B,C,H,W)
    #pragma unroll
    for (int mi = 0; mi < 4; mi++) {
        #pragma unroll
        for (int ni = 0; ni < 6; ni++) {
            float* a4 = acc[mi][ni];
            const int m0 = M0 + wm * 64 + mi * 16 + g;
            const int m1 = m0 + 8;
            const int n0 = wn * 48 + ni * 8 + 2 * cq;
            float b0 = bias1[n0], b1 = bias1[n0 + 1];
            float2 r0 = *(const float2*)&resid[(size_t)m0 * CH + n0];
            float2 r1 = *(const float2*)&resid[(size_t)m1 * CH + n0];
            int bb = m0 >> 16;
            int hw = m0 & 65535;
            size_t c0 = ((size_t)(bb * CH + n0)     << 16);
            size_t c1 = ((size_t)(bb * CH + n0 + 1) << 16);
            out[c0 + hw]     = a4[0] + b0 + r0.x;
            out[c1 + hw]     = a4[1] + b1 + r0.y;
            out[c0 + hw + 8] = a4[2] + b0 + r1.x;
            out[c1 + hw + 8] = a4[3] + b1 + r1.y;
        }
    }
}

// ---------------------------------------------------------------------------
// Kernel 3: window attention. Block = window, 768 threads:
// thread = (head h, row r, half) — each half handles 16 of 32 dims, dot
// combined with one shfl. Scores are bounded (|s| < ~1), so softmax needs
// no max subtraction: exp cannot overflow; result is shift-invariant.
// ---------------------------------------------------------------------------
__global__ __launch_bounds__(768)
void attn_kernel(const float* __restrict__ qkv,
                 const float* __restrict__ bias_table,
                 float* __restrict__ obuf)
{
    extern __shared__ float smatt[];
    float* ks  = smatt;                 // [64][192]
    float* vs  = smatt + 64 * 192;      // [64][192]
    float* bsm = vs + 64 * 192;         // [6][225]

    const int bw   = blockIdx.x;
    const int tid  = threadIdx.x;
    const int half = tid & 1;
    const int r    = (tid >> 1) & 63;
    const int h    = tid >> 7;
    const float* base = qkv + (size_t)bw * WN * (3 * CH);

    #pragma unroll
    for (int it = 0; it < 4; it++) {
        int f = tid + it * 768;           // 0..3071
        int row = f / 48, j = (f % 48) * 4;
        *(float4*)&ks[row * 192 + j] = *(const float4*)(base + (size_t)row * 576 + 192 + j);
        *(float4*)&vs[row * 192 + j] = *(const float4*)(base + (size_t)row * 576 + 384 + j);
    }
    for (int i = tid; i < 6 * 225; i += 768) {
        int hh = i / 225, e = i % 225;
        bsm[i] = bias_table[e * 6 + hh];
    }

    const float scale = 0.17677669529663687f; // 32^-0.5
    float q[16];
    const float* qrow = base + (size_t)r * 576 + h * 32 + half * 16;
    #pragma unroll
    for (int d = 0; d < 16; d++) q[d] = qrow[d] * scale;
    __syncthreads();

    const int it7 = (r >> 3) + 7, jt7 = (r & 7) + 7;
    const float* kh = ks + h * 32 + half * 16;
    const float* vh = vs + h * 32 + half * 16;
    const float* bh = bsm + h * 225;

    float sum = 0.f;
    float o[16];
    #pragma unroll
    for (int d = 0; d < 16; d++) o[d] = 0.f;

    #pragma unroll 4
    for (int m = 0; m < WN; m++) {
        const float4* km = (const float4*)(kh + m * 192);
        float4 k0 = km[0], k1 = km[1], k2 = km[2], k3 = km[3];
        float a0 = q[0]*k0.x + q[1]*k0.y + q[2]*k0.z + q[3]*k0.w;
        float a1 = q[4]*k1.x + q[5]*k1.y + q[6]*k1.z + q[7]*k1.w;
        float a2 = q[8]*k2.x + q[9]*k2.y + q[10]*k2.z + q[11]*k2.w;
        float a3 = q[12]*k3.x + q[13]*k3.y + q[14]*k3.z + q[15]*k3.w;
        float ah = (a0 + a1) + (a2 + a3);
        float a  = ah + __shfl_xor_sync(0xffffffffu, ah, 1);
        a += bh[(it7 - (m >> 3)) * 15 + (jt7 - (m & 7))];
        float p = __expf(a);
        sum += p;
        const float4* vm = (const float4*)(vh + m * 192);
        float4 v0 = vm[0], v1 = vm[1], v2 = vm[2], v3 = vm[3];
        o[0]+=p*v0.x; o[1]+=p*v0.y; o[2]+=p*v0.z; o[3]+=p*v0.w;
        o[4]+=p*v1.x; o[5]+=p*v1.y; o[6]+=p*v1.z; o[7]+=p*v1.w;
        o[8]+=p*v2.x; o[9]+=p*v2.y; o[10]+=p*v2.z; o[11]+=p*v2.w;
        o[12]+=p*v3.x; o[13]+=p*v3.y; o[14]+=p*v3.z; o[15]+=p*v3.w;
    }
    float inv = 1.f / sum;
    float* orow = obuf + ((size_t)bw * WN + r) * CH + h * 32 + half * 16;
    #pragma unroll
    for (int d4 = 0; d4 < 4; d4++)
        *(float4*)(orow + d4 * 4) = make_float4(o[d4*4]*inv, o[d4*4+1]*inv,
                                                o[d4*4+2]*inv, o[d4*4+3]*inv);
}

// ---------------------------------------------------------------------------
// Kernel 4: LN2 over 192-rows of y (window layout) + window_reverse
// ---------------------------------------------------------------------------
__global__ __launch_bounds__(256)
void ln2_kernel(const float* __restrict__ y,
                const float* __restrict__ g,
                const float* __restrict__ b,
                float* __restrict__ zt)
{
    int tid  = threadIdx.x;
    int lane = tid & 31, wid = tid >> 5;
    int row  = blockIdx.x * 8 + wid;
    const float* yr = y + (size_t)row * CH;

    float v[6];
    float sum = 0.f, sq = 0.f;
    #pragma unroll
    for (int k = 0; k < 6; k++) {
        v[k] = yr[lane + k * 32];
        sum += v[k]; sq += v[k] * v[k];
    }
    #pragma unroll
    for (int o = 16; o > 0; o >>= 1) {
        sum += __shfl_xor_sync(0xffffffffu, sum, o);
        sq  += __shfl_xor_sync(0xffffffffu, sq,  o);
    }
    float mean = sum * (1.f / CH);
    float var  = sq * (1.f / CH) - mean * mean;
    float inv  = rsqrtf(fmaxf(var, 0.f) + 1e-5f);

    int d4 = row & 7, d3 = (row >> 3) & 7, d2 = (row >> 6) & 31,
        d1 = (row >> 11) & 31, bb = row >> 16;
    int h = d1 * 8 + d3, w = d2 * 8 + d4;
    int t = ((bb * 256 + h) << 8) + w;
    float* zr = zt + (size_t)t * CH;
    #pragma unroll
    for (int k = 0; k < 6; k++) {
        int c = lane + k * 32;
        zr[c] = (v[k] - mean) * inv * g[c] + b[c];
    }
}

// ---------------------------------------------------------------------------
// kernel_launch
// ---------------------------------------------------------------------------
extern "C" void kernel_launch(void* const* d_in, const int* in_sizes, int n_in,
                              void* d_out, int out_size)
{
    const float* x          = (const float*)d_in[0];
    const float* ln1_g      = (const float*)d_in[1];
    const float* ln1_b      = (const float*)d_in[2];
    const float* qkv_w      = (const float*)d_in[3];
    const float* qkv_b      = (const float*)d_in[4];
    const float* bias_table = (const float*)d_in[5];
    const float* proj_w     = (const float*)d_in[6];
    const float* proj_b     = (const float*)d_in[7];
    const float* ln2_g      = (const float*)d_in[8];
    const float* ln2_b      = (const float*)d_in[9];
    const float* fc1_w      = (const float*)d_in[10];
    const float* fc1_b      = (const float*)d_in[11];
    const float* fc2_w      = (const float*)d_in[12];
    const float* fc2_b      = (const float*)d_in[13];
    const float* fc3_w      = (const float*)d_in[14];
    const float* fc3_b      = (const float*)d_in[15];
    float* out = (float*)d_out;

    float *perm, *qkv, *obuf, *ybuf, *zt, *gbuf, *qT, *pT, *wI;
    cudaGetSymbolAddress((void**)&perm, d_perm);
    cudaGetSymbolAddress((void**)&qkv,  d_qkv);
    cudaGetSymbolAddress((void**)&obuf, d_obuf);
    cudaGetSymbolAddress((void**)&ybuf, d_ybuf);
    cudaGetSymbolAddress((void**)&zt,   d_zt);
    cudaGetSymbolAddress((void**)&gbuf, d_gbuf);
    cudaGetSymbolAddress((void**)&qT,   d_qkvT);
    cudaGetSymbolAddress((void**)&pT,   d_projT);
    cudaGetSymbolAddress((void**)&wI,   d_wI);

    const int SMEM_LN1  = 192 * 256 * 4;                       // 196608
    const int SMEM_K192 = (128 + 2 * 64) * AS_STRIDE * 4;      // 200704
    const int SMEM_OUT  = 2 * (128 + 192) * 20 * 4;            // 51200
    const int SMEM_ATTN = (64 * 192 * 2 + 6 * 225) * 4;        // 103704

    cudaFuncSetAttribute(ln1_kernel,   cudaFuncAttributeMaxDynamicSharedMemorySize, SMEM_LN1);
    cudaFuncSetAttribute(gemm_k192<0>, cudaFuncAttributeMaxDynamicSharedMemorySize, SMEM_K192);
    cudaFuncSetAttribute(gemm_k192<1>, cudaFuncAttributeMaxDynamicSharedMemorySize, SMEM_K192);
    cudaFuncSetAttribute(gemm_k192<2>, cudaFuncAttributeMaxDynamicSharedMemorySize, SMEM_K192);
    cudaFuncSetAttribute(gemm_out,     cudaFuncAttributeMaxDynamicSharedMemorySize, SMEM_OUT);
    cudaFuncSetAttribute(attn_kernel,  cudaFuncAttributeMaxDynamicSharedMemorySize, SMEM_ATTN);

    // 1) LN1 + window-partition permute; weight prep
    ln1_kernel<<<NTOK / 256, 256, SMEM_LN1>>>(x, ln1_g, ln1_b, perm);
    prep_w<<<(768 * 192 + 255) / 256, 256>>>(qkv_w, proj_w, fc1_w, fc2_w, qT, pT, wI);

    // 2) QKV GEMM: (131072,192) @ (576,192)^T
    gemm_k192<0><<<1024, 128, SMEM_K192>>>(perm, qT, qkv_b, nullptr, nullptr, qkv, 576);

    // 3) window attention
    attn_kernel<<<NWIN, 768, SMEM_ATTN>>>(qkv, bias_table, obuf);

    // 4) proj GEMM + residual
    gemm_k192<1><<<1024, 128, SMEM_K192>>>(obuf, pT, proj_b, nullptr, perm, ybuf, 192);

    // 5) LN2 + window_reverse -> token-major z
    ln2_kernel<<<NTOK / 8, 256>>>(ybuf, ln2_g, ln2_b, zt);

    // 6) gated FFN (interleaved dual) -> gbuf [M,768]
    gemm_k192<2><<<1024, 128, SMEM_K192>>>(zt, wI, fc1_b, fc2_b, nullptr, gbuf, 1536);

    // 7) FFN out GEMM + residual(z), scatter to (B,C,H,W)
    gemm_out<<<1024, 256, SMEM_OUT>>>(gbuf, fc3_w, fc3_b, zt, out);
}

// round 10
// speedup vs baseline: 1.9721x; 1.9721x over previous
#include <cuda_runtime.h>
#include <cuda_fp16.h>
#include <cstdint>

// ---------------------------------------------------------------------------
// Problem constants (B=2, C=192, H=W=256, WS=8, NH=6, hd=32, DF=768)
// ---------------------------------------------------------------------------
#define CH    192
#define NTOK  131072
#define DF    768
#define NWIN  2048
#define WN    64

// ---------------------------------------------------------------------------
// Scratch (static device allocations)
// ---------------------------------------------------------------------------
__device__ float  d_perm32[NTOK * CH];       // LN1 out fp32 (residual master)
__device__ __half d_perm16[NTOK * CH];       // LN1 out fp16 (GEMM A)
__device__ __half d_qkv16 [NTOK * 3 * CH];
__device__ __half d_obuf16[NTOK * CH];       // attention out (GEMM A)
__device__ float  d_ybuf  [NTOK * CH];       // proj + residual (fp32)
__device__ float  d_zt32  [NTOK * CH];       // LN2 out fp32 (residual master)
__device__ __half d_zt16  [NTOK * CH];       // LN2 out fp16 (GEMM A)
__device__ __half d_gbuf16[NTOK * DF];
__device__ __half d_qT16  [576 * 192];
__device__ __half d_pT16  [192 * 192];
__device__ __half d_wI16  [1536 * 192];      // interleaved fc1/fc2
__device__ __half d_f3_16 [192 * 768];

// ---------------------------------------------------------------------------
// mma.sync / cp.async helpers (portable PTX)
// ---------------------------------------------------------------------------
__device__ __forceinline__ void mma_f16(float* d, const uint32_t* a, const uint32_t* b) {
    asm volatile(
        "mma.sync.aligned.m16n8k16.row.col.f32.f16.f16.f32 "
        "{%0,%1,%2,%3},{%4,%5,%6,%7},{%8,%9},{%0,%1,%2,%3};"
        : "+f"(d[0]), "+f"(d[1]), "+f"(d[2]), "+f"(d[3])
        : "r"(a[0]), "r"(a[1]), "r"(a[2]), "r"(a[3]), "r"(b[0]), "r"(b[1]));
}
__device__ __forceinline__ void cp_async16(void* dst, const void* src) {
    uint32_t d = (uint32_t)__cvta_generic_to_shared(dst);
    asm volatile("cp.async.cg.shared.global [%0], [%1], 16;" :: "r"(d), "l"(src));
}
__device__ __forceinline__ void cp_commit() { asm volatile("cp.async.commit_group;"); }
template<int N>
__device__ __forceinline__ void cp_wait() { asm volatile("cp.async.wait_group %0;" :: "n"(N)); }

// ---------------------------------------------------------------------------
// Kernel 1: LN1 + channel-layout window partition; writes fp32 + fp16 copies.
// Block = one (b,h) row of 256 pixels; x staged in smem (read once).
// ---------------------------------------------------------------------------
__global__ void ln1_kernel(const float* __restrict__ x,
                           const float* __restrict__ g,
                           const float* __restrict__ b,
                           float* __restrict__ p32,
                           __half* __restrict__ p16)
{
    extern __shared__ float xs[];     // [192][256]
    const int tid = threadIdx.x;      // = w
    const int h  = blockIdx.x & 255;
    const int bb = blockIdx.x >> 8;
    const float* xp = x + (size_t)bb * CH * 65536 + h * 256 + tid;

    float sum = 0.f, sq = 0.f;
    #pragma unroll 4
    for (int c = 0; c < CH; c++) {
        float v = xp[(size_t)c * 65536];
        xs[c * 256 + tid] = v;
        sum += v; sq += v * v;
    }
    float mean = sum * (1.f / CH);
    float var  = sq * (1.f / CH) - mean * mean;
    float inv  = rsqrtf(fmaxf(var, 0.f) + 1e-5f);

    const int h1 = h >> 3, h2 = h & 7;
    #pragma unroll 4
    for (int c = 0; c < CH; c++) {
        float v = (xs[c * 256 + tid] - mean) * inv * g[c] + b[c];
        int c1 = c >> 3, c2 = c & 7;
        size_t P = (((((size_t)bb * 24 + c1) * 32 + h1) * 8 + c2) * 8 + h2) * 256 + tid;
        p32[P] = v;
        p16[P] = __float2half_rn(v);
    }
}

// ---------------------------------------------------------------------------
// Kernel 2: weight prep — transpose + fp16 convert; interleave fc1/fc2 rows
// ---------------------------------------------------------------------------
__global__ void prep_w(const float* __restrict__ qw, const float* __restrict__ pw,
                       const float* __restrict__ f1, const float* __restrict__ f2,
                       const float* __restrict__ f3,
                       __half* __restrict__ qT, __half* __restrict__ pT,
                       __half* __restrict__ wI, __half* __restrict__ f3h)
{
    int i = blockIdx.x * blockDim.x + threadIdx.x;
    if (i < 192 * 576) { int k = i / 576, n = i % 576; qT[n * 192 + k] = __float2half_rn(qw[i]); }
    if (i < 192 * 192) { int k = i / 192, n = i % 192; pT[n * 192 + k] = __float2half_rn(pw[i]); }
    if (i < 768 * 192) {
        int j = i / 192, k = i % 192;
        wI[(size_t)(2 * j)     * 192 + k] = __float2half_rn(f1[i]);
        wI[(size_t)(2 * j + 1) * 192 + k] = __float2half_rn(f2[i]);
    }
    if (i < 192 * 768) f3h[i] = __float2half_rn(f3[i]);
}

// ---------------------------------------------------------------------------
// fp16 mma.sync GEMM: C[M,N] = A[M,K] @ Bw[N,K]^T   (A,Bw fp16, acc fp32)
// block tile 128x64, 4 warps (2x2), warp tile 64x32 (4x4 of m16n8k16).
// BK=32, cp.async double-buffered, smem rows 40 halves (bank-conflict-free).
// EPI: 0 = +bias                  -> half out[M,N]   (QKV)
//      1 = +bias + resid[m*N+n]   -> f32  out[M,N]   (proj + residual)
//      2 = gate: sigmoid(c0+b1)*(c1+b2) -> half out[M,768] (gated FFN, wI)
//      3 = +bias + resid[m*192+n] -> f32 scatter (B,C,H,W)
// ---------------------------------------------------------------------------
template<int EPI>
__global__ __launch_bounds__(128)
void mma_gemm(const __half* __restrict__ A,  const __half* __restrict__ Bw,
              const float* __restrict__ bias1, const float* __restrict__ bias2,
              const float* __restrict__ resid, void* __restrict__ outv,
              int N, int K)
{
    __shared__ __half As[2][128][40];
    __shared__ __half Bs[2][64][40];

    const int tid  = threadIdx.x;
    const int warp = tid >> 5, lane = tid & 31;
    const int g = lane >> 2, cq = lane & 3;
    const int wm = warp >> 1, wn = warp & 1;
    const int M0 = blockIdx.y * 128, N0 = blockIdx.x * 64;

    float acc[4][4][4] = {};
    const int NC = K >> 5;

    // prefetch stage 0 (BK=32 halves per row; 16B = 8 halves per cp.async)
    {
        #pragma unroll
        for (int it = 0; it < 4; it++) {
            int f = tid + it * 128, row = f >> 2, grp = f & 3;
            cp_async16(&As[0][row][grp * 8], A + (size_t)(M0 + row) * K + grp * 8);
        }
        #pragma unroll
        for (int it = 0; it < 2; it++) {
            int f = tid + it * 128, row = f >> 2, grp = f & 3;
            cp_async16(&Bs[0][row][grp * 8], Bw + (size_t)(N0 + row) * K + grp * 8);
        }
    }
    cp_commit();

    for (int c = 0; c < NC; c++) {
        if (c + 1 < NC) {
            const int s = (c + 1) & 1, k0 = (c + 1) << 5;
            #pragma unroll
            for (int it = 0; it < 4; it++) {
                int f = tid + it * 128, row = f >> 2, grp = f & 3;
                cp_async16(&As[s][row][grp * 8], A + (size_t)(M0 + row) * K + k0 + grp * 8);
            }
            #pragma unroll
            for (int it = 0; it < 2; it++) {
                int f = tid + it * 128, row = f >> 2, grp = f & 3;
                cp_async16(&Bs[s][row][grp * 8], Bw + (size_t)(N0 + row) * K + k0 + grp * 8);
            }
        }
        cp_commit();
        cp_wait<1>();          // stage c complete
        __syncthreads();

        const int s = c & 1;
        #pragma unroll
        for (int ks = 0; ks < 2; ks++) {   // two k16 steps per BK=32
            const int k16 = ks * 16;
            uint32_t af[4][4], bf[4][2];
            #pragma unroll
            for (int mi = 0; mi < 4; mi++) {
                int r0 = wm * 64 + mi * 16 + g;
                af[mi][0] = *(const uint32_t*)&As[s][r0    ][k16 + 2 * cq];
                af[mi][1] = *(const uint32_t*)&As[s][r0 + 8][k16 + 2 * cq];
                af[mi][2] = *(const uint32_t*)&As[s][r0    ][k16 + 2 * cq + 8];
                af[mi][3] = *(const uint32_t*)&As[s][r0 + 8][k16 + 2 * cq + 8];
            }
            #pragma unroll
            for (int ni = 0; ni < 4; ni++) {
                int n0 = wn * 32 + ni * 8 + g;
                bf[ni][0] = *(const uint32_t*)&Bs[s][n0][k16 + 2 * cq];
                bf[ni][1] = *(const uint32_t*)&Bs[s][n0][k16 + 2 * cq + 8];
            }
            #pragma unroll
            for (int mi = 0; mi < 4; mi++)
                #pragma unroll
                for (int ni = 0; ni < 4; ni++)
                    mma_f16(acc[mi][ni], af[mi], bf[ni]);
        }
        __syncthreads();
    }

    // ---- epilogue ----
    __half* outh = (__half*)outv;
    float*  outf = (float*)outv;
    #pragma unroll
    for (int mi = 0; mi < 4; mi++) {
        #pragma unroll
        for (int ni = 0; ni < 4; ni++) {
            float* a4 = acc[mi][ni];
            const int m0 = M0 + wm * 64 + mi * 16 + g;
            const int m1 = m0 + 8;
            const int n0 = N0 + wn * 32 + ni * 8 + 2 * cq;

            if (EPI == 0) {
                float b0 = bias1[n0], b1 = bias1[n0 + 1];
                *(__half2*)&outh[(size_t)m0 * N + n0] = __floats2half2_rn(a4[0] + b0, a4[1] + b1);
                *(__half2*)&outh[(size_t)m1 * N + n0] = __floats2half2_rn(a4[2] + b0, a4[3] + b1);
            } else if (EPI == 1) {
                float b0 = bias1[n0], b1 = bias1[n0 + 1];
                float2 r0 = *(const float2*)&resid[(size_t)m0 * N + n0];
                float2 r1 = *(const float2*)&resid[(size_t)m1 * N + n0];
                *(float2*)&outf[(size_t)m0 * N + n0] =
                    make_float2(a4[0] + b0 + r0.x, a4[1] + b1 + r0.y);
                *(float2*)&outf[(size_t)m1 * N + n0] =
                    make_float2(a4[2] + b0 + r1.x, a4[3] + b1 + r1.y);
            } else if (EPI == 2) {
                // interleaved gate pair p at cols (2p, 2p+1)
                int p = ((N0 + wn * 32 + ni * 8) >> 1) + cq;
                float b1 = bias1[p], b2 = bias2[p];
                float h1a = 1.f / (1.f + __expf(-(a4[0] + b1)));
                float h1b = 1.f / (1.f + __expf(-(a4[2] + b1)));
                outh[(size_t)m0 * DF + p] = __float2half_rn(h1a * (a4[1] + b2));
                outh[(size_t)m1 * DF + p] = __float2half_rn(h1b * (a4[3] + b2));
            } else { // EPI == 3: +bias +resid, scatter to (B,C,H,W), fp32 out
                float b0 = bias1[n0], b1 = bias1[n0 + 1];
                float2 r0 = *(const float2*)&resid[(size_t)m0 * CH + n0];
                float2 r1 = *(const float2*)&resid[(size_t)m1 * CH + n0];
                int bb = m0 >> 16;
                int hw = m0 & 65535;
                size_t c0 = ((size_t)(bb * CH + n0)     << 16);
                size_t c1 = ((size_t)(bb * CH + n0 + 1) << 16);
                outf[c0 + hw]     = a4[0] + b0 + r0.x;
                outf[c1 + hw]     = a4[1] + b1 + r0.y;
                outf[c0 + hw + 8] = a4[2] + b0 + r1.x;
                outf[c1 + hw + 8] = a4[3] + b1 + r1.y;
            }
        }
    }
}

// ---------------------------------------------------------------------------
// Kernel 3: window attention (fp16 qkv in, fp16 out). Block = window,
// 768 threads = (head, row, half): 16 dims each, dot combined via shfl.
// Scores bounded -> softmax without max subtraction (shift-invariant).
// ---------------------------------------------------------------------------
__global__ __launch_bounds__(768)
void attn_kernel(const __half* __restrict__ qkv,
                 const float* __restrict__ bias_table,
                 __half* __restrict__ obuf)
{
    extern __shared__ float smatt[];
    float* ks  = smatt;                 // [64][192]
    float* vs  = smatt + 64 * 192;      // [64][192]
    float* bsm = vs + 64 * 192;         // [6][225]

    const int bw   = blockIdx.x;
    const int tid  = threadIdx.x;
    const int half = tid & 1;
    const int r    = (tid >> 1) & 63;
    const int h    = tid >> 7;
    const __half* base = qkv + (size_t)bw * WN * (3 * CH);

    // load K,V: 64 rows x 192 halves each; 16B = 8 halves per chunk
    #pragma unroll
    for (int it = 0; it < 2; it++) {
        int f = tid + it * 768;           // 0..1535
        int row = f / 24, j = (f % 24) * 8;
        uint4 kr = *(const uint4*)(base + (size_t)row * 576 + 192 + j);
        uint4 vr = *(const uint4*)(base + (size_t)row * 576 + 384 + j);
        const __half2* kh2 = (const __half2*)&kr;
        const __half2* vh2 = (const __half2*)&vr;
        #pragma unroll
        for (int t = 0; t < 4; t++) {
            float2 kf = __half22float2(kh2[t]);
            float2 vf = __half22float2(vh2[t]);
            ks[row * 192 + j + 2 * t]     = kf.x;
            ks[row * 192 + j + 2 * t + 1] = kf.y;
            vs[row * 192 + j + 2 * t]     = vf.x;
            vs[row * 192 + j + 2 * t + 1] = vf.y;
        }
    }
    for (int i = tid; i < 6 * 225; i += 768) {
        int hh = i / 225, e = i % 225;
        bsm[i] = bias_table[e * 6 + hh];
    }

    const float scale = 0.17677669529663687f; // 32^-0.5
    float q[16];
    const __half* qrow = base + (size_t)r * 576 + h * 32 + half * 16;
    #pragma unroll
    for (int d = 0; d < 16; d++) q[d] = __half2float(qrow[d]) * scale;
    __syncthreads();

    const int it7 = (r >> 3) + 7, jt7 = (r & 7) + 7;
    const float* kh = ks + h * 32 + half * 16;
    const float* vh = vs + h * 32 + half * 16;
    const float* bh = bsm + h * 225;

    float sum = 0.f;
    float o[16];
    #pragma unroll
    for (int d = 0; d < 16; d++) o[d] = 0.f;

    #pragma unroll 4
    for (int m = 0; m < WN; m++) {
        const float4* km = (const float4*)(kh + m * 192);
        float4 k0 = km[0], k1 = km[1], k2 = km[2], k3 = km[3];
        float a0 = q[0]*k0.x + q[1]*k0.y + q[2]*k0.z + q[3]*k0.w;
        float a1 = q[4]*k1.x + q[5]*k1.y + q[6]*k1.z + q[7]*k1.w;
        float a2 = q[8]*k2.x + q[9]*k2.y + q[10]*k2.z + q[11]*k2.w;
        float a3 = q[12]*k3.x + q[13]*k3.y + q[14]*k3.z + q[15]*k3.w;
        float ah = (a0 + a1) + (a2 + a3);
        float a  = ah + __shfl_xor_sync(0xffffffffu, ah, 1);
        a += bh[(it7 - (m >> 3)) * 15 + (jt7 - (m & 7))];
        float p = __expf(a);
        sum += p;
        const float4* vm = (const float4*)(vh + m * 192);
        float4 v0 = vm[0], v1 = vm[1], v2 = vm[2], v3 = vm[3];
        o[0]+=p*v0.x; o[1]+=p*v0.y; o[2]+=p*v0.z; o[3]+=p*v0.w;
        o[4]+=p*v1.x; o[5]+=p*v1.y; o[6]+=p*v1.z; o[7]+=p*v1.w;
        o[8]+=p*v2.x; o[9]+=p*v2.y; o[10]+=p*v2.z; o[11]+=p*v2.w;
        o[12]+=p*v3.x; o[13]+=p*v3.y; o[14]+=p*v3.z; o[15]+=p*v3.w;
    }
    float inv = 1.f / sum;
    __half* orow = obuf + ((size_t)bw * WN + r) * CH + h * 32 + half * 16;
    #pragma unroll
    for (int d2 = 0; d2 < 8; d2++)
        *(__half2*)(orow + d2 * 2) = __floats2half2_rn(o[d2*2] * inv, o[d2*2+1] * inv);
}

// ---------------------------------------------------------------------------
// Kernel 4: LN2 over 192-rows of y (window layout) + window_reverse;
// dual write fp32 + fp16.
// ---------------------------------------------------------------------------
__global__ __launch_bounds__(256)
void ln2_kernel(const float* __restrict__ y,
                const float* __restrict__ g,
                const float* __restrict__ b,
                float* __restrict__ z32,
                __half* __restrict__ z16)
{
    int tid  = threadIdx.x;
    int lane = tid & 31, wid = tid >> 5;
    int row  = blockIdx.x * 8 + wid;
    const float* yr = y + (size_t)row * CH;

    float v[6];
    float sum = 0.f, sq = 0.f;
    #pragma unroll
    for (int k = 0; k < 6; k++) {
        v[k] = yr[lane + k * 32];
        sum += v[k]; sq += v[k] * v[k];
    }
    #pragma unroll
    for (int o = 16; o > 0; o >>= 1) {
        sum += __shfl_xor_sync(0xffffffffu, sum, o);
        sq  += __shfl_xor_sync(0xffffffffu, sq,  o);
    }
    float mean = sum * (1.f / CH);
    float var  = sq * (1.f / CH) - mean * mean;
    float inv  = rsqrtf(fmaxf(var, 0.f) + 1e-5f);

    int d4 = row & 7, d3 = (row >> 3) & 7, d2 = (row >> 6) & 31,
        d1 = (row >> 11) & 31, bb = row >> 16;
    int h = d1 * 8 + d3, w = d2 * 8 + d4;
    int t = ((bb * 256 + h) << 8) + w;
    #pragma unroll
    for (int k = 0; k < 6; k++) {
        int c = lane + k * 32;
        float val = (v[k] - mean) * inv * g[c] + b[c];
        z32[(size_t)t * CH + c] = val;
        z16[(size_t)t * CH + c] = __float2half_rn(val);
    }
}

// ---------------------------------------------------------------------------
// kernel_launch
// ---------------------------------------------------------------------------
extern "C" void kernel_launch(void* const* d_in, const int* in_sizes, int n_in,
                              void* d_out, int out_size)
{
    const float* x          = (const float*)d_in[0];
    const float* ln1_g      = (const float*)d_in[1];
    const float* ln1_b      = (const float*)d_in[2];
    const float* qkv_w      = (const float*)d_in[3];
    const float* qkv_b      = (const float*)d_in[4];
    const float* bias_table = (const float*)d_in[5];
    const float* proj_w     = (const float*)d_in[6];
    const float* proj_b     = (const float*)d_in[7];
    const float* ln2_g      = (const float*)d_in[8];
    const float* ln2_b      = (const float*)d_in[9];
    const float* fc1_w      = (const float*)d_in[10];
    const float* fc1_b      = (const float*)d_in[11];
    const float* fc2_w      = (const float*)d_in[12];
    const float* fc2_b      = (const float*)d_in[13];
    const float* fc3_w      = (const float*)d_in[14];
    const float* fc3_b      = (const float*)d_in[15];
    float* out = (float*)d_out;

    float  *perm32, *ybuf, *zt32;
    __half *perm16, *qkv16, *obuf16, *zt16, *gbuf16, *qT, *pT, *wI, *f3h;
    cudaGetSymbolAddress((void**)&perm32, d_perm32);
    cudaGetSymbolAddress((void**)&perm16, d_perm16);
    cudaGetSymbolAddress((void**)&qkv16,  d_qkv16);
    cudaGetSymbolAddress((void**)&obuf16, d_obuf16);
    cudaGetSymbolAddress((void**)&ybuf,   d_ybuf);
    cudaGetSymbolAddress((void**)&zt32,   d_zt32);
    cudaGetSymbolAddress((void**)&zt16,   d_zt16);
    cudaGetSymbolAddress((void**)&gbuf16, d_gbuf16);
    cudaGetSymbolAddress((void**)&qT,     d_qT16);
    cudaGetSymbolAddress((void**)&pT,     d_pT16);
    cudaGetSymbolAddress((void**)&wI,     d_wI16);
    cudaGetSymbolAddress((void**)&f3h,    d_f3_16);

    const int SMEM_LN1  = 192 * 256 * 4;                 // 196608
    const int SMEM_ATTN = (64 * 192 * 2 + 6 * 225) * 4;  // 103704
    cudaFuncSetAttribute(ln1_kernel,  cudaFuncAttributeMaxDynamicSharedMemorySize, SMEM_LN1);
    cudaFuncSetAttribute(attn_kernel, cudaFuncAttributeMaxDynamicSharedMemorySize, SMEM_ATTN);

    // 1) LN1 + window-partition permute (fp32 + fp16); weight prep
    ln1_kernel<<<NTOK / 256, 256, SMEM_LN1>>>(x, ln1_g, ln1_b, perm32, perm16);
    prep_w<<<(768 * 192 + 255) / 256, 256>>>(qkv_w, proj_w, fc1_w, fc2_w, fc3_w,
                                             qT, pT, wI, f3h);

    // 2) QKV GEMM: (131072,192) @ (576,192)^T -> fp16
    mma_gemm<0><<<dim3(9, 1024), 128>>>(perm16, qT, qkv_b, nullptr, nullptr, qkv16, 576, 192);

    // 3) window attention -> fp16
    attn_kernel<<<NWIN, 768, SMEM_ATTN>>>(qkv16, bias_table, obuf16);

    // 4) proj GEMM + residual(perm32) -> fp32 ybuf
    mma_gemm<1><<<dim3(3, 1024), 128>>>(obuf16, pT, proj_b, nullptr, perm32, ybuf, 192, 192);

    // 5) LN2 + window_reverse -> zt32 + zt16
    ln2_kernel<<<NTOK / 8, 256>>>(ybuf, ln2_g, ln2_b, zt32, zt16);

    // 6) gated FFN (interleaved dual) -> gbuf16 [M,768]
    mma_gemm<2><<<dim3(24, 1024), 128>>>(zt16, wI, fc1_b, fc2_b, nullptr, gbuf16, 1536, 192);

    // 7) FFN out GEMM + residual(zt32), scatter to (B,C,H,W) fp32
    mma_gemm<3><<<dim3(3, 1024), 128>>>(gbuf16, f3h, fc3_b, nullptr, zt32, out, 192, 768);
}

// round 14
// speedup vs baseline: 2.0629x; 1.0460x over previous
#include <cuda_runtime.h>
#include <cuda_fp16.h>
#include <cstdint>

// ---------------------------------------------------------------------------
// Problem constants (B=2, C=192, H=W=256, WS=8, NH=6, hd=32, DF=768)
// ---------------------------------------------------------------------------
#define CH    192
#define NTOK  131072
#define DF    768
#define NWIN  2048
#define WN    64

// ---------------------------------------------------------------------------
// Scratch (static device allocations)
// ---------------------------------------------------------------------------
__device__ float  d_perm32[NTOK * CH];       // LN1 out fp32 (residual master)
__device__ __half d_perm16[NTOK * CH];       // LN1 out fp16 (GEMM A)
__device__ __half d_qkv16 [NTOK * 3 * CH];
__device__ __half d_obuf16[NTOK * CH];       // attention out (GEMM A)
__device__ float  d_ybuf  [NTOK * CH];       // proj + residual (fp32)
__device__ float  d_zt32  [NTOK * CH];       // LN2 out fp32 (residual master)
__device__ __half d_zt16  [NTOK * CH];       // LN2 out fp16 (GEMM A)
__device__ __half d_gbuf16[NTOK * DF];
__device__ __half d_qT16  [576 * 192];
__device__ __half d_pT16  [192 * 192];
__device__ __half d_wI16  [1536 * 192];      // interleaved fc1/fc2
__device__ __half d_f3_16 [192 * 768];

// ---------------------------------------------------------------------------
// mma.sync / ldmatrix / cp.async helpers (portable PTX, no arch-a features)
// ---------------------------------------------------------------------------
__device__ __forceinline__ void mma_f16(float* d, const uint32_t* a, const uint32_t* b) {
    asm volatile(
        "mma.sync.aligned.m16n8k16.row.col.f32.f16.f16.f32 "
        "{%0,%1,%2,%3},{%4,%5,%6,%7},{%8,%9},{%0,%1,%2,%3};"
        : "+f"(d[0]), "+f"(d[1]), "+f"(d[2]), "+f"(d[3])
        : "r"(a[0]), "r"(a[1]), "r"(a[2]), "r"(a[3]), "r"(b[0]), "r"(b[1]));
}
__device__ __forceinline__ void ldsm_x4(uint32_t* r, uint32_t addr) {
    asm volatile("ldmatrix.sync.aligned.m8n8.x4.shared.b16 {%0,%1,%2,%3}, [%4];"
        : "=r"(r[0]), "=r"(r[1]), "=r"(r[2]), "=r"(r[3]) : "r"(addr));
}
__device__ __forceinline__ void cp_async16(void* dst, const void* src) {
    uint32_t d = (uint32_t)__cvta_generic_to_shared(dst);
    asm volatile("cp.async.cg.shared.global [%0], [%1], 16;" :: "r"(d), "l"(src));
}
__device__ __forceinline__ void cp_commit() { asm volatile("cp.async.commit_group;"); }
template<int N>
__device__ __forceinline__ void cp_wait() { asm volatile("cp.async.wait_group %0;" :: "n"(N)); }

// ---------------------------------------------------------------------------
// Kernel 1: LN1 + channel-layout window partition; writes fp32 + fp16 copies.
// ---------------------------------------------------------------------------
__global__ void ln1_kernel(const float* __restrict__ x,
                           const float* __restrict__ g,
                           const float* __restrict__ b,
                           float* __restrict__ p32,
                           __half* __restrict__ p16)
{
    extern __shared__ float xs[];     // [192][256]
    const int tid = threadIdx.x;      // = w
    const int h  = blockIdx.x & 255;
    const int bb = blockIdx.x >> 8;
    const float* xp = x + (size_t)bb * CH * 65536 + h * 256 + tid;

    float sum = 0.f, sq = 0.f;
    #pragma unroll 4
    for (int c = 0; c < CH; c++) {
        float v = xp[(size_t)c * 65536];
        xs[c * 256 + tid] = v;
        sum += v; sq += v * v;
    }
    float mean = sum * (1.f / CH);
    float var  = sq * (1.f / CH) - mean * mean;
    float inv  = rsqrtf(fmaxf(var, 0.f) + 1e-5f);

    const int h1 = h >> 3, h2 = h & 7;
    #pragma unroll 4
    for (int c = 0; c < CH; c++) {
        float v = (xs[c * 256 + tid] - mean) * inv * g[c] + b[c];
        int c1 = c >> 3, c2 = c & 7;
        size_t P = (((((size_t)bb * 24 + c1) * 32 + h1) * 8 + c2) * 8 + h2) * 256 + tid;
        p32[P] = v;
        p16[P] = __float2half_rn(v);
    }
}

// ---------------------------------------------------------------------------
// Kernel 2: weight prep — transpose + fp16 convert; interleave fc1/fc2 rows
// ---------------------------------------------------------------------------
__global__ void prep_w(const float* __restrict__ qw, const float* __restrict__ pw,
                       const float* __restrict__ f1, const float* __restrict__ f2,
                       const float* __restrict__ f3,
                       __half* __restrict__ qT, __half* __restrict__ pT,
                       __half* __restrict__ wI, __half* __restrict__ f3h)
{
    int i = blockIdx.x * blockDim.x + threadIdx.x;
    if (i < 192 * 576) { int k = i / 576, n = i % 576; qT[n * 192 + k] = __float2half_rn(qw[i]); }
    if (i < 192 * 192) { int k = i / 192, n = i % 192; pT[n * 192 + k] = __float2half_rn(pw[i]); }
    if (i < 768 * 192) {
        int j = i / 192, k = i % 192;
        wI[(size_t)(2 * j)     * 192 + k] = __float2half_rn(f1[i]);
        wI[(size_t)(2 * j + 1) * 192 + k] = __float2half_rn(f2[i]);
    }
    if (i < 192 * 768) f3h[i] = __float2half_rn(f3[i]);
}

// ---------------------------------------------------------------------------
// fp16 mma.sync GEMM: C[M,N] = A[M,K] @ Bw[N,K]^T  (fp16 in, fp32 acc)
// Block 128x96, 4 warps (2x2), warp tile 64x48 (4m x 6n of m16n8k16).
// BK=32, cp.async double-buffered, rows of 40 halves (conflict-free for
// both cp.async stores and ldmatrix reads). Fragments via ldmatrix.x4.
// EPI: 0 = +bias                  -> half out[M,N]   (QKV)
//      1 = +bias + resid[m*N+n]   -> f32  out[M,N]   (proj + residual)
//      2 = gate: sigmoid(c0+b1)*(c1+b2) -> half out[M,768] (gated FFN, wI)
//      3 = +bias + resid[m*192+n] -> f32 scatter (B,C,H,W)
// ---------------------------------------------------------------------------
template<int EPI>
__global__ __launch_bounds__(128)
void mma_gemm(const __half* __restrict__ A,  const __half* __restrict__ Bw,
              const float* __restrict__ bias1, const float* __restrict__ bias2,
              const float* __restrict__ resid, void* __restrict__ outv,
              int N, int K)
{
    __shared__ __half As[2][128][40];
    __shared__ __half Bs[2][96][40];

    const int tid  = threadIdx.x;
    const int warp = tid >> 5, lane = tid & 31;
    const int g = lane >> 2, cq = lane & 3;
    const int wm = warp >> 1, wn = warp & 1;
    const int M0 = blockIdx.y * 128, N0 = blockIdx.x * 96;

    float acc[4][6][4] = {};
    const int NC = K >> 5;

    // ldmatrix per-lane base addresses
    const uint32_t asBase = (uint32_t)__cvta_generic_to_shared(&As[0][0][0]);
    const uint32_t bsBase = (uint32_t)__cvta_generic_to_shared(&Bs[0][0][0]);
    // A x4: rows (lane&15), col-8-block (lane>>4)
    const uint32_t aAddr0 = asBase +
        (((uint32_t)(wm * 64 + (lane & 15))) * 40 + (uint32_t)(lane >> 4) * 8) * 2;
    // B x4: rows (lane&7)+((lane>>4)<<3), col-8-block (lane>>3)&1
    const uint32_t bAddr0 = bsBase +
        (((uint32_t)(wn * 48 + (lane & 7) + ((lane >> 4) << 3))) * 40 +
         (uint32_t)((lane >> 3) & 1) * 8) * 2;

    // --- stage-0 prefetch ---
    {
        #pragma unroll
        for (int it = 0; it < 4; it++) {           // A: 128 rows x 4 x 16B
            int f = tid + it * 128, row = f >> 2, grp = f & 3;
            cp_async16(&As[0][row][grp * 8], A + (size_t)(M0 + row) * K + grp * 8);
        }
        #pragma unroll
        for (int it = 0; it < 3; it++) {           // B: 96 rows x 4 x 16B
            int f = tid + it * 128, row = f >> 2, grp = f & 3;
            cp_async16(&Bs[0][row][grp * 8], Bw + (size_t)(N0 + row) * K + grp * 8);
        }
    }
    cp_commit();

    for (int c = 0; c < NC; c++) {
        if (c + 1 < NC) {
            const int s = (c + 1) & 1, k0 = (c + 1) << 5;
            #pragma unroll
            for (int it = 0; it < 4; it++) {
                int f = tid + it * 128, row = f >> 2, grp = f & 3;
                cp_async16(&As[s][row][grp * 8], A + (size_t)(M0 + row) * K + k0 + grp * 8);
            }
            #pragma unroll
            for (int it = 0; it < 3; it++) {
                int f = tid + it * 128, row = f >> 2, grp = f & 3;
                cp_async16(&Bs[s][row][grp * 8], Bw + (size_t)(N0 + row) * K + k0 + grp * 8);
            }
        }
        cp_commit();
        cp_wait<1>();          // stage c complete
        __syncthreads();

        const int s = c & 1;
        const uint32_t aS = aAddr0 + (uint32_t)s * (128 * 40 * 2);
        const uint32_t bS = bAddr0 + (uint32_t)s * (96 * 40 * 2);
        #pragma unroll
        for (int ks = 0; ks < 2; ks++) {   // two k16 steps per BK=32
            uint32_t a[4][4], b[3][4];
            #pragma unroll
            for (int mi = 0; mi < 4; mi++)
                ldsm_x4(a[mi], aS + (uint32_t)(mi * 16 * 40 + ks * 16) * 2);
            #pragma unroll
            for (int nj = 0; nj < 3; nj++)
                ldsm_x4(b[nj], bS + (uint32_t)(nj * 16 * 40 + ks * 16) * 2);
            #pragma unroll
            for (int mi = 0; mi < 4; mi++)
                #pragma unroll
                for (int ni = 0; ni < 6; ni++)
                    mma_f16(acc[mi][ni], a[mi], &b[ni >> 1][(ni & 1) * 2]);
        }
        __syncthreads();
    }

    // ---- epilogue ----
    __half* outh = (__half*)outv;
    float*  outf = (float*)outv;
    #pragma unroll
    for (int mi = 0; mi < 4; mi++) {
        #pragma unroll
        for (int ni = 0; ni < 6; ni++) {
            float* a4 = acc[mi][ni];
            const int m0 = M0 + wm * 64 + mi * 16 + g;
            const int m1 = m0 + 8;
            const int n0 = N0 + wn * 48 + ni * 8 + 2 * cq;

            if (EPI == 0) {
                float b0 = bias1[n0], b1 = bias1[n0 + 1];
                *(__half2*)&outh[(size_t)m0 * N + n0] = __floats2half2_rn(a4[0] + b0, a4[1] + b1);
                *(__half2*)&outh[(size_t)m1 * N + n0] = __floats2half2_rn(a4[2] + b0, a4[3] + b1);
            } else if (EPI == 1) {
                float b0 = bias1[n0], b1 = bias1[n0 + 1];
                float2 r0 = *(const float2*)&resid[(size_t)m0 * N + n0];
                float2 r1 = *(const float2*)&resid[(size_t)m1 * N + n0];
                *(float2*)&outf[(size_t)m0 * N + n0] =
                    make_float2(a4[0] + b0 + r0.x, a4[1] + b1 + r0.y);
                *(float2*)&outf[(size_t)m1 * N + n0] =
                    make_float2(a4[2] + b0 + r1.x, a4[3] + b1 + r1.y);
            } else if (EPI == 2) {
                // interleaved gate pair p at cols (2p, 2p+1)
                int p = ((N0 + wn * 48 + ni * 8) >> 1) + cq;
                float b1 = bias1[p], b2 = bias2[p];
                float h1a = 1.f / (1.f + __expf(-(a4[0] + b1)));
                float h1b = 1.f / (1.f + __expf(-(a4[2] + b1)));
                outh[(size_t)m0 * DF + p] = __float2half_rn(h1a * (a4[1] + b2));
                outh[(size_t)m1 * DF + p] = __float2half_rn(h1b * (a4[3] + b2));
            } else { // EPI == 3: +bias +resid, scatter to (B,C,H,W), fp32 out
                float b0 = bias1[n0], b1 = bias1[n0 + 1];
                float2 r0 = *(const float2*)&resid[(size_t)m0 * CH + n0];
                float2 r1 = *(const float2*)&resid[(size_t)m1 * CH + n0];
                int bb = m0 >> 16;
                int hw = m0 & 65535;
                size_t c0 = ((size_t)(bb * CH + n0)     << 16);
                size_t c1 = ((size_t)(bb * CH + n0 + 1) << 16);
                outf[c0 + hw]     = a4[0] + b0 + r0.x;
                outf[c1 + hw]     = a4[1] + b1 + r0.y;
                outf[c0 + hw + 8] = a4[2] + b0 + r1.x;
                outf[c1 + hw + 8] = a4[3] + b1 + r1.y;
            }
        }
    }
}

// ---------------------------------------------------------------------------
// Kernel 3: window attention (fp16 qkv in, fp16 out). Block = window,
// 768 threads = (head, row, half): 16 dims each, dot combined via shfl.
// Scores bounded -> softmax without max subtraction (shift-invariant).
// ---------------------------------------------------------------------------
__global__ __launch_bounds__(768)
void attn_kernel(const __half* __restrict__ qkv,
                 const float* __restrict__ bias_table,
                 __half* __restrict__ obuf)
{
    extern __shared__ float smatt[];
    float* ks  = smatt;                 // [64][192]
    float* vs  = smatt + 64 * 192;      // [64][192]
    float* bsm = vs + 64 * 192;         // [6][225]

    const int bw   = blockIdx.x;
    const int tid  = threadIdx.x;
    const int half = tid & 1;
    const int r    = (tid >> 1) & 63;
    const int h    = tid >> 7;
    const __half* base = qkv + (size_t)bw * WN * (3 * CH);

    #pragma unroll
    for (int it = 0; it < 2; it++) {
        int f = tid + it * 768;           // 0..1535
        int row = f / 24, j = (f % 24) * 8;
        uint4 kr = *(const uint4*)(base + (size_t)row * 576 + 192 + j);
        uint4 vr = *(const uint4*)(base + (size_t)row * 576 + 384 + j);
        const __half2* kh2 = (const __half2*)&kr;
        const __half2* vh2 = (const __half2*)&vr;
        #pragma unroll
        for (int t = 0; t < 4; t++) {
            float2 kf = __half22float2(kh2[t]);
            float2 vf = __half22float2(vh2[t]);
            ks[row * 192 + j + 2 * t]     = kf.x;
            ks[row * 192 + j + 2 * t + 1] = kf.y;
            vs[row * 192 + j + 2 * t]     = vf.x;
            vs[row * 192 + j + 2 * t + 1] = vf.y;
        }
    }
    for (int i = tid; i < 6 * 225; i += 768) {
        int hh = i / 225, e = i % 225;
        bsm[i] = bias_table[e * 6 + hh];
    }

    const float scale = 0.17677669529663687f; // 32^-0.5
    float q[16];
    const __half* qrow = base + (size_t)r * 576 + h * 32 + half * 16;
    #pragma unroll
    for (int d = 0; d < 16; d++) q[d] = __half2float(qrow[d]) * scale;
    __syncthreads();

    const int it7 = (r >> 3) + 7, jt7 = (r & 7) + 7;
    const float* kh = ks + h * 32 + half * 16;
    const float* vh = vs + h * 32 + half * 16;
    const float* bh = bsm + h * 225;

    float sum = 0.f;
    float o[16];
    #pragma unroll
    for (int d = 0; d < 16; d++) o[d] = 0.f;

    #pragma unroll 4
    for (int m = 0; m < WN; m++) {
        const float4* km = (const float4*)(kh + m * 192);
        float4 k0 = km[0], k1 = km[1], k2 = km[2], k3 = km[3];
        float a0 = q[0]*k0.x + q[1]*k0.y + q[2]*k0.z + q[3]*k0.w;
        float a1 = q[4]*k1.x + q[5]*k1.y + q[6]*k1.z + q[7]*k1.w;
        float a2 = q[8]*k2.x + q[9]*k2.y + q[10]*k2.z + q[11]*k2.w;
        float a3 = q[12]*k3.x + q[13]*k3.y + q[14]*k3.z + q[15]*k3.w;
        float ah = (a0 + a1) + (a2 + a3);
        float a  = ah + __shfl_xor_sync(0xffffffffu, ah, 1);
        a += bh[(it7 - (m >> 3)) * 15 + (jt7 - (m & 7))];
        float p = __expf(a);
        sum += p;
        const float4* vm = (const float4*)(vh + m * 192);
        float4 v0 = vm[0], v1 = vm[1], v2 = vm[2], v3 = vm[3];
        o[0]+=p*v0.x; o[1]+=p*v0.y; o[2]+=p*v0.z; o[3]+=p*v0.w;
        o[4]+=p*v1.x; o[5]+=p*v1.y; o[6]+=p*v1.z; o[7]+=p*v1.w;
        o[8]+=p*v2.x; o[9]+=p*v2.y; o[10]+=p*v2.z; o[11]+=p*v2.w;
        o[12]+=p*v3.x; o[13]+=p*v3.y; o[14]+=p*v3.z; o[15]+=p*v3.w;
    }
    float inv = 1.f / sum;
    __half* orow = obuf + ((size_t)bw * WN + r) * CH + h * 32 + half * 16;
    #pragma unroll
    for (int d2 = 0; d2 < 8; d2++)
        *(__half2*)(orow + d2 * 2) = __floats2half2_rn(o[d2*2] * inv, o[d2*2+1] * inv);
}

// ---------------------------------------------------------------------------
// Kernel 4: LN2 over 192-rows of y (window layout) + window_reverse;
// dual write fp32 + fp16.
// ---------------------------------------------------------------------------
__global__ __launch_bounds__(256)
void ln2_kernel(const float* __restrict__ y,
                const float* __restrict__ g,
                const float* __restrict__ b,
                float* __restrict__ z32,
                __half* __restrict__ z16)
{
    int tid  = threadIdx.x;
    int lane = tid & 31, wid = tid >> 5;
    int row  = blockIdx.x * 8 + wid;
    const float* yr = y + (size_t)row * CH;

    float v[6];
    float sum = 0.f, sq = 0.f;
    #pragma unroll
    for (int k = 0; k < 6; k++) {
        v[k] = yr[lane + k * 32];
        sum += v[k]; sq += v[k] * v[k];
    }
    #pragma unroll
    for (int o = 16; o > 0; o >>= 1) {
        sum += __shfl_xor_sync(0xffffffffu, sum, o);
        sq  += __shfl_xor_sync(0xffffffffu, sq,  o);
    }
    float mean = sum * (1.f / CH);
    float var  = sq * (1.f / CH) - mean * mean;
    float inv  = rsqrtf(fmaxf(var, 0.f) + 1e-5f);

    int d4 = row & 7, d3 = (row >> 3) & 7, d2 = (row >> 6) & 31,
        d1 = (row >> 11) & 31, bb = row >> 16;
    int h = d1 * 8 + d3, w = d2 * 8 + d4;
    int t = ((bb * 256 + h) << 8) + w;
    #pragma unroll
    for (int k = 0; k < 6; k++) {
        int c = lane + k * 32;
        float val = (v[k] - mean) * inv * g[c] + b[c];
        z32[(size_t)t * CH + c] = val;
        z16[(size_t)t * CH + c] = __float2half_rn(val);
    }
}

// ---------------------------------------------------------------------------
// kernel_launch
// ---------------------------------------------------------------------------
extern "C" void kernel_launch(void* const* d_in, const int* in_sizes, int n_in,
                              void* d_out, int out_size)
{
    const float* x          = (const float*)d_in[0];
    const float* ln1_g      = (const float*)d_in[1];
    const float* ln1_b      = (const float*)d_in[2];
    const float* qkv_w      = (const float*)d_in[3];
    const float* qkv_b      = (const float*)d_in[4];
    const float* bias_table = (const float*)d_in[5];
    const float* proj_w     = (const float*)d_in[6];
    const float* proj_b     = (const float*)d_in[7];
    const float* ln2_g      = (const float*)d_in[8];
    const float* ln2_b      = (const float*)d_in[9];
    const float* fc1_w      = (const float*)d_in[10];
    const float* fc1_b      = (const float*)d_in[11];
    const float* fc2_w      = (const float*)d_in[12];
    const float* fc2_b      = (const float*)d_in[13];
    const float* fc3_w      = (const float*)d_in[14];
    const float* fc3_b      = (const float*)d_in[15];
    float* out = (float*)d_out;

    float  *perm32, *ybuf, *zt32;
    __half *perm16, *qkv16, *obuf16, *zt16, *gbuf16, *qT, *pT, *wI, *f3h;
    cudaGetSymbolAddress((void**)&perm32, d_perm32);
    cudaGetSymbolAddress((void**)&perm16, d_perm16);
    cudaGetSymbolAddress((void**)&qkv16,  d_qkv16);
    cudaGetSymbolAddress((void**)&obuf16, d_obuf16);
    cudaGetSymbolAddress((void**)&ybuf,   d_ybuf);
    cudaGetSymbolAddress((void**)&zt32,   d_zt32);
    cudaGetSymbolAddress((void**)&zt16,   d_zt16);
    cudaGetSymbolAddress((void**)&gbuf16, d_gbuf16);
    cudaGetSymbolAddress((void**)&qT,     d_qT16);
    cudaGetSymbolAddress((void**)&pT,     d_pT16);
    cudaGetSymbolAddress((void**)&wI,     d_wI16);
    cudaGetSymbolAddress((void**)&f3h,    d_f3_16);

    const int SMEM_LN1  = 192 * 256 * 4;                 // 196608
    const int SMEM_ATTN = (64 * 192 * 2 + 6 * 225) * 4;  // 103704
    cudaFuncSetAttribute(ln1_kernel,  cudaFuncAttributeMaxDynamicSharedMemorySize, SMEM_LN1);
    cudaFuncSetAttribute(attn_kernel, cudaFuncAttributeMaxDynamicSharedMemorySize, SMEM_ATTN);

    // 1) LN1 + window-partition permute (fp32 + fp16); weight prep
    ln1_kernel<<<NTOK / 256, 256, SMEM_LN1>>>(x, ln1_g, ln1_b, perm32, perm16);
    prep_w<<<(768 * 192 + 255) / 256, 256>>>(qkv_w, proj_w, fc1_w, fc2_w, fc3_w,
                                             qT, pT, wI, f3h);

    // 2) QKV GEMM: (131072,192) @ (576,192)^T -> fp16
    mma_gemm<0><<<dim3(6, 1024), 128>>>(perm16, qT, qkv_b, nullptr, nullptr, qkv16, 576, 192);

    // 3) window attention -> fp16
    attn_kernel<<<NWIN, 768, SMEM_ATTN>>>(qkv16, bias_table, obuf16);

    // 4) proj GEMM + residual(perm32) -> fp32 ybuf
    mma_gemm<1><<<dim3(2, 1024), 128>>>(obuf16, pT, proj_b, nullptr, perm32, ybuf, 192, 192);

    // 5) LN2 + window_reverse -> zt32 + zt16
    ln2_kernel<<<NTOK / 8, 256>>>(ybuf, ln2_g, ln2_b, zt32, zt16);

    // 6) gated FFN (interleaved dual) -> gbuf16 [M,768]
    mma_gemm<2><<<dim3(16, 1024), 128>>>(zt16, wI, fc1_b, fc2_b, nullptr, gbuf16, 1536, 192);

    // 7) FFN out GEMM + residual(zt32), scatter to (B,C,H,W) fp32
    mma_gemm<3><<<dim3(2, 1024), 128>>>(gbuf16, f3h, fc3_b, nullptr, zt32, out, 192, 768);
}